// round 14
// baseline (speedup 1.0000x reference)
#include <cuda_runtime.h>
#include <cstdint>

// Problem constants
#define NXC 64
#define NYC 64
#define SCALE 16
#define PP 15
#define BB 4
#define CC 3
#define HH 1024
#define WW 1024
#define HW (HH*WW)
#define NNODES 4096
#define CHW (CC*HH*WW)
#define NPAIRS_HALF (BB * 63 * 64)      // 16128
#define NPAIRS (2 * NPAIRS_HALF)        // 32256
static const long long A_ELEMS = (long long)BB * NNODES * NNODES;  // 67108864

#define EDGE_BLOCKS 256                  // static: one per (b, y) strip, at t=0
#define TOTAL_BLOCKS 1184                // 148 SMs x 8 blocks = one wave
#define THREADS 256
#define CHUNK_F4 1024                    // 16KB item = one A row / 4 image rows

// Steal queue: [0, 3072) copy chunks, [3072, 19456) A rows.
#define COPY_ITEMS 3072
#define NA_ROWS 16384
#define NITEMS (COPY_ITEMS + NA_ROWS)

// Edge scratch (summed over channels): [0,16128) dv, [16128,32256) dh
__device__ float    g_scratch[NPAIRS];
__device__ unsigned g_chunk = 0;         // work-stealing counter
__device__ unsigned g_edges_done = 0;    // completed edge blocks (0..256)
__device__ unsigned g_done = 0;          // block completion counter

__global__ void __launch_bounds__(THREADS, 8)
fused_kernel(const float* __restrict__ data,
             float4* __restrict__ out,
             long long a4) {
    const float4* src = (const float4*)data;
    const float4 z = make_float4(0.f, 0.f, 0.f, 0.f);
    int tid = threadIdx.x;

    // ===================== static edge phase (blocks 0..255) =====================
    if (blockIdx.x < EDGE_BLOCKS) {
        int e = blockIdx.x;
        int b = e >> 6;
        int y = e & 63;
        int x = tid >> 2;            // cell column bin
        int q = tid & 3;             // quarter (q==3 masks col 15)
        bool has_v = (y < 63);
        bool has_h = (x < 63);

        const float4* base0 = (const float4*)(data + (long long)b * CHW
                                                    + (long long)(y * SCALE) * WW);
        float sv = 0.f, sh = 0.f;
        #pragma unroll
        for (int c = 0; c < CC; c++) {
            const float4* cb = base0 + (long long)c * (HW / 4);
            #pragma unroll 5
            for (int i = 0; i < PP; i++) {
                const float4* rp = cb + i * (WW / 4);
                float4 a = __ldg(rp + tid);
                if (has_v) {
                    float4 v = __ldg(rp + 4096 + tid);     // +16 rows
                    sv += fabsf(a.x - v.x) + fabsf(a.y - v.y) + fabsf(a.z - v.z);
                    if (q < 3) sv += fabsf(a.w - v.w);
                }
                if (has_h) {
                    float4 hh = __ldg(rp + tid + 4);       // +16 cols
                    sh += fabsf(a.x - hh.x) + fabsf(a.y - hh.y) + fabsf(a.z - hh.z);
                    if (q < 3) sh += fabsf(a.w - hh.w);
                }
            }
        }
        sv += __shfl_xor_sync(0xffffffffu, sv, 1);
        sv += __shfl_xor_sync(0xffffffffu, sv, 2);
        sh += __shfl_xor_sync(0xffffffffu, sh, 1);
        sh += __shfl_xor_sync(0xffffffffu, sh, 2);
        if (q == 0) {
            if (has_v) g_scratch[b * 4032 + y * 64 + x] = sv;
            if (has_h) g_scratch[NPAIRS_HALF + b * 4032 + y * 63 + x] = sh;
        }
        __syncthreads();
        if (tid == 0) {
            __threadfence();                 // publish scratch before counting
            atomicAdd(&g_edges_done, 1u);
        }
    }

    // ===================== work-stealing fill / copy / patch =====================
    __shared__ unsigned s_next;
    bool edges_ok = false;                   // per-thread one-time readiness flag

    if (tid == 0) s_next = atomicAdd(&g_chunk, 1u);
    __syncthreads();
    unsigned w = s_next;

    while (w < NITEMS) {
        if (tid == 0) s_next = atomicAdd(&g_chunk, 1u);   // prefetch next item

        if (w < COPY_ITEMS) {
            // -------- copy chunk (16KB, exact fit) --------
            long long sidx = (long long)w * CHUNK_F4 + tid;
            #pragma unroll
            for (int k = 0; k < CHUNK_F4 / THREADS; k++)
                __stcs(&out[a4 + sidx + k * THREADS], src[sidx + k * THREADS]);
        } else {
            // -------- A row: barrier-free zeros + same-thread overwrite patch ----
            unsigned r = w - COPY_ITEMS;                   // global A row 0..16383
            int b = r >> 12;
            int n = r & 4095;
            int y = n >> 6, x = n & 63;
            float4* row4 = out + (long long)r * CHUNK_F4;

            // Prologue: do I own one of the <=4 special elements of this row?
            // element e -> owner tid (e>>2)&255, chunk pk = e>>10, comp e&3.
            float4 pv = z;
            int pk = -1;
            {
                int e[4];  float val[4];  bool ok[4];
                int base = b * 4032;
                e[0] = n - 64; ok[0] = (y > 0);
                val[0] = ok[0] ? __ldg(&g_scratch[base + (y - 1) * 64 + x]) : 0.f;
                e[1] = n + 64; ok[1] = (y < 63);
                val[1] = ok[1] ? __ldg(&g_scratch[base + y * 64 + x]) : 0.f;
                e[2] = n - 1;  ok[2] = (x > 0);
                val[2] = ok[2] ? __ldg(&g_scratch[NPAIRS_HALF + base + y * 63 + x - 1]) : 0.f;
                e[3] = n + 1;  ok[3] = (x < 63);
                val[3] = ok[3] ? __ldg(&g_scratch[NPAIRS_HALF + base + y * 63 + x]) : 0.f;
                bool mine = false;
                #pragma unroll
                for (int j = 0; j < 4; j++)
                    mine |= (ok[j] && (((e[j] >> 2) & 255) == tid));
                if (mine) {
                    if (!edges_ok) {       // one-time per thread; edges finish early
                        while (*(volatile unsigned*)&g_edges_done < EDGE_BLOCKS) { }
                        __threadfence();   // acquire scratch
                        edges_ok = true;
                    }
                    #pragma unroll
                    for (int j = 0; j < 4; j++) {
                        if (ok[j] && (((e[j] >> 2) & 255) == tid)) {
                            // reload after the fence for the first-time path
                            float v;
                            int bb2 = b * 4032;
                            if (j == 0)      v = g_scratch[bb2 + (y - 1) * 64 + x];
                            else if (j == 1) v = g_scratch[bb2 + y * 64 + x];
                            else if (j == 2) v = g_scratch[NPAIRS_HALF + bb2 + y * 63 + x - 1];
                            else             v = g_scratch[NPAIRS_HALF + bb2 + y * 63 + x];
                            pk = e[j] >> 10;
                            int comp = e[j] & 3;
                            if (comp == 0)      pv.x = v;
                            else if (comp == 1) pv.y = v;
                            else if (comp == 2) pv.z = v;
                            else                pv.w = v;
                        }
                    }
                }
                (void)val;
            }

            // Stream zeros (unconditional, uniform across warp)
            #pragma unroll
            for (int k = 0; k < CHUNK_F4 / THREADS; k++)
                __stcs(&row4[tid + k * THREADS], z);
            // Same-thread, same-address overwrite: program order guarantees it lands.
            if (pk >= 0)
                __stcs(&row4[tid + pk * THREADS], pv);
        }

        __syncthreads();                     // protect s_next for next iteration
        w = s_next;
    }

    // ===================== epilogue: reset counters for next replay =====================
    if (tid == 0) {
        unsigned d = atomicAdd(&g_done, 1u);
        if (d == TOTAL_BLOCKS - 1) {
            g_chunk = 0;
            g_edges_done = 0;
            g_done = 0;
        }
    }
}

extern "C" void kernel_launch(void* const* d_in, const int* in_sizes, int n_in,
                              void* d_out, int out_size) {
    const float* data = (const float*)d_in[0];
    float* out = (float*)d_out;

    long long a_elems = A_ELEMS;
    long long total = (long long)out_size;
    if (total < a_elems) a_elems = total;
    long long a4 = a_elems >> 2;

    fused_kernel<<<TOTAL_BLOCKS, THREADS>>>(data, (float4*)out, a4);
}